// round 2
// baseline (speedup 1.0000x reference)
#include <cuda_runtime.h>
#include <math.h>

#define Nn 100000
#define Ee 3200000
#define Cc 64
#define ALPHA_CORR 0.979f
#define ALPHA_SMOOTH 0.756f
#define SCAN_BLK 1024
#define SCAN_NBLK ((Nn + SCAN_BLK - 1) / SCAN_BLK)   // 98

// ---------------- static scratch (no dynamic allocation allowed) ----------------
__device__ float g_bufA[Nn * Cc];
__device__ float g_bufB[Nn * Cc];
__device__ float g_last[Nn * Cc];
__device__ int   g_deg[Nn];
__device__ int   g_cnt[Nn];
__device__ int   g_rowptr[Nn + 1];
__device__ float g_norm[Nn];
__device__ int   g_csr_src[Ee];
__device__ float g_csr_w[Ee];
__device__ int   g_blocksums[128];
__device__ float g_sumabs;
__device__ float g_nummask;
__device__ int   g_mask_mode;   // 0=uint8, 1=int32, 2=float32

// ---------------- mask dtype detection ----------------
__global__ void k_detect(const void* __restrict__ mp) {
    if (threadIdx.x == 0 && blockIdx.x == 0) {
        const int*   ip = (const int*)mp;
        const float* fp = (const float*)mp;
        bool i_ok = true, f_ok = true;
        for (int i = 0; i < 1024; i++) {
            int v = ip[i];
            if (v != 0 && v != 1) i_ok = false;
            float f = fp[i];
            if (!(f == 0.0f || f == 1.0f)) f_ok = false;
        }
        g_mask_mode = i_ok ? 1 : (f_ok ? 2 : 0);
    }
}

__device__ __forceinline__ bool mask_at(const void* __restrict__ mp, int i) {
    int mode = g_mask_mode;
    if (mode == 1) return ((const int*)mp)[i] != 0;
    if (mode == 2) return ((const float*)mp)[i] != 0.0f;
    return ((const unsigned char*)mp)[i] != 0;
}

// ---------------- preprocessing ----------------
__global__ void k_init() {
    int i = blockIdx.x * blockDim.x + threadIdx.x;
    if (i < Nn) { g_deg[i] = 0; g_cnt[i] = 0; }
    if (i == 0) { g_sumabs = 0.f; g_nummask = 0.f; }
}

__global__ void k_hist(const int* __restrict__ dst) {
    int i = blockIdx.x * blockDim.x + threadIdx.x;
    if (i < Ee) atomicAdd(&g_deg[dst[i]], 1);
}

__global__ void k_scan_a() {
    __shared__ int sh[SCAN_BLK];
    int t = threadIdx.x;
    int i = blockIdx.x * SCAN_BLK + t;
    int v = (i < Nn) ? g_deg[i] : 0;
    sh[t] = v;
    __syncthreads();
    for (int off = 1; off < SCAN_BLK; off <<= 1) {
        int x = (t >= off) ? sh[t - off] : 0;
        __syncthreads();
        sh[t] += x;
        __syncthreads();
    }
    if (i < Nn) g_rowptr[i] = sh[t] - v;      // exclusive within block
    if (t == SCAN_BLK - 1) g_blocksums[blockIdx.x] = sh[t];
}

__global__ void k_scan_b() {
    int acc = 0;
    for (int b = 0; b < SCAN_NBLK; b++) {
        int s = g_blocksums[b];
        g_blocksums[b] = acc;
        acc += s;
    }
}

__global__ void k_scan_c() {
    int i = blockIdx.x * blockDim.x + threadIdx.x;
    if (i < Nn) g_rowptr[i] += g_blocksums[i / SCAN_BLK];
    if (i == 0) g_rowptr[Nn] = Ee;
}

__global__ void k_norm() {
    int i = blockIdx.x * blockDim.x + threadIdx.x;
    if (i < Nn) {
        float d = (float)g_deg[i];
        if (d < 1.f) d = 1.f;
        g_norm[i] = rsqrtf(d);
    }
}

__global__ void k_fill(const int* __restrict__ src, const int* __restrict__ dst) {
    int i = blockIdx.x * blockDim.x + threadIdx.x;
    if (i >= Ee) return;
    int d = dst[i];
    int s = src[i];
    int pos = g_rowptr[d] + atomicAdd(&g_cnt[d], 1);
    g_csr_src[pos] = s;
    g_csr_w[pos] = g_norm[s] * g_norm[d];
}

// ---------------- error + global reductions ----------------
__global__ void k_error(const float* __restrict__ ys, const float* __restrict__ yt,
                        const void* __restrict__ mask) {
    int idx = blockIdx.x * blockDim.x + threadIdx.x;
    float a = 0.f, cm = 0.f;
    if (idx < Nn * Cc) {
        int n = idx >> 6;
        float m = mask_at(mask, n) ? 1.f : 0.f;
        float e = m * (yt[idx] - ys[idx]);
        g_bufA[idx] = e;
        g_last[idx] = (1.f - ALPHA_CORR) * e;
        a = fabsf(e);
        if ((idx & (Cc - 1)) == 0) cm = m;
    }
    for (int o = 16; o; o >>= 1) {
        a  += __shfl_down_sync(0xffffffffu, a, o);
        cm += __shfl_down_sync(0xffffffffu, cm, o);
    }
    __shared__ float sa[8], sc[8];
    int warp = threadIdx.x >> 5, lane = threadIdx.x & 31;
    if (lane == 0) { sa[warp] = a; sc[warp] = cm; }
    __syncthreads();
    if (threadIdx.x == 0) {
        float ta = 0.f, tc = 0.f;
        int nw = blockDim.x >> 5;
        for (int w = 0; w < nw; w++) { ta += sa[w]; tc += sc[w]; }
        atomicAdd(&g_sumabs, ta);
        atomicAdd(&g_nummask, tc);
    }
}

// ---------------- combine (scale + blend) ----------------
__global__ void k_combine(const float* __restrict__ ys, const float* __restrict__ yt,
                          const void* __restrict__ mask) {
    int w = (blockIdx.x * blockDim.x + threadIdx.x) >> 5;
    int lane = threadIdx.x & 31;
    if (w >= Nn) return;
    int base = w * Cc + 2 * lane;
    float2 sm = *(const float2*)(g_bufA + base);
    float part = fabsf(sm.x) + fabsf(sm.y);
    for (int o = 16; o; o >>= 1) part += __shfl_xor_sync(0xffffffffu, part, o);
    float sigma = g_sumabs / g_nummask;
    float scale = sigma / part;
    if (isinf(scale) || scale > 1000.f) scale = 1.f;
    float2 s = *(const float2*)(ys + base);
    float rx = s.x + scale * sm.x; if (isnan(rx)) rx = s.x;
    float ry = s.y + scale * sm.y; if (isnan(ry)) ry = s.y;
    if (mask_at(mask, w)) {
        float2 t = *(const float2*)(yt + base);
        rx = t.x; ry = t.y;
    }
    float2 outv = make_float2(rx, ry);
    *(float2*)(g_bufB + base) = outv;
    float2 lv = make_float2((1.f - ALPHA_SMOOTH) * rx, (1.f - ALPHA_SMOOTH) * ry);
    *(float2*)(g_last + base) = lv;
}

// ---------------- one propagation layer: warp per dst node ----------------
__global__ void k_prop(const float* __restrict__ yin, float* __restrict__ yout,
                       const float* __restrict__ last, float alpha, float lo, float hi) {
    int w = (blockIdx.x * blockDim.x + threadIdx.x) >> 5;
    int lane = threadIdx.x & 31;
    if (w >= Nn) return;
    int s0 = g_rowptr[w];
    int s1 = g_rowptr[w + 1];
    int nE = s1 - s0;
    float2 acc[4];
    acc[0] = make_float2(0.f, 0.f);
    acc[1] = make_float2(0.f, 0.f);
    acc[2] = make_float2(0.f, 0.f);
    acc[3] = make_float2(0.f, 0.f);

    for (int base = 0; base < nE; base += 32) {
        int e = s0 + base + lane;
        int sv = 0;
        float wv = 0.f;
        if (base + lane < nE) {
            sv = g_csr_src[e];
            wv = g_csr_w[e];
        }
        int cnt = nE - base;
        if (cnt > 32) cnt = 32;
        int cntr = (cnt + 3) & ~3;   // padded lanes have wv=0 (safe reads of row 0)
        for (int j = 0; j < cntr; j += 4) {
#pragma unroll
            for (int u = 0; u < 4; u++) {
                int   ss = __shfl_sync(0xffffffffu, sv, j + u);
                float ww = __shfl_sync(0xffffffffu, wv, j + u);
                const float2 v = __ldg((const float2*)(yin + (size_t)ss * Cc) + lane);
                acc[u].x = fmaf(ww, v.x, acc[u].x);
                acc[u].y = fmaf(ww, v.y, acc[u].y);
            }
        }
    }
    float ax = (acc[0].x + acc[1].x) + (acc[2].x + acc[3].x);
    float ay = (acc[0].y + acc[1].y) + (acc[2].y + acc[3].y);

    const float2 l = __ldg((const float2*)(last + (size_t)w * Cc) + lane);
    float2 o;
    o.x = fminf(fmaxf(fmaf(alpha, ax, l.x), lo), hi);
    o.y = fminf(fmaxf(fmaf(alpha, ay, l.y), lo), hi);
    *((float2*)(yout + (size_t)w * Cc) + lane) = o;
}

// ---------------- launch ----------------
extern "C" void kernel_launch(void* const* d_in, const int* in_sizes, int n_in,
                              void* d_out, int out_size) {
    const float* y_soft = (const float*)d_in[0];
    const float* y_true = (const float*)d_in[1];
    const int*   src    = (const int*)d_in[2];
    const int*   dst    = (const int*)d_in[3];
    const void*  mask   = (const void*)d_in[4];
    float* out = (float*)d_out;

    const int T = 256;
    const int gN  = (Nn + T - 1) / T;
    const int gE  = (Ee + T - 1) / T;
    const int gNC = (Nn * Cc + T - 1) / T;
    const int gW  = (Nn * 32 + T - 1) / T;   // warp-per-node grids

    float* bufA; float* bufB; float* lastp;
    cudaGetSymbolAddress((void**)&bufA, g_bufA);
    cudaGetSymbolAddress((void**)&bufB, g_bufB);
    cudaGetSymbolAddress((void**)&lastp, g_last);

    // --- mask dtype detection ---
    k_detect<<<1, 32>>>(mask);

    // --- preprocessing: degrees, CSR, norms ---
    k_init<<<gN, T>>>();
    k_hist<<<gE, T>>>(dst);
    k_scan_a<<<SCAN_NBLK, SCAN_BLK>>>();
    k_scan_b<<<1, 1>>>();
    k_scan_c<<<gN, T>>>();
    k_norm<<<gN, T>>>();
    k_fill<<<gE, T>>>(src, dst);

    // --- error + sums ---
    k_error<<<gNC, T>>>(y_soft, y_true, mask);

    // --- correction propagate: 10 layers, result ends in bufA ---
    {
        float* in = bufA; float* outp = bufB;
        for (int l = 0; l < 10; l++) {
            k_prop<<<gW, T>>>(in, outp, lastp, ALPHA_CORR, -1.f, 1.f);
            float* t = in; in = outp; outp = t;
        }
    }

    // --- combine: reads bufA (smoothed error), writes bufB (y), sets g_last ---
    k_combine<<<gW, T>>>(y_soft, y_true, mask);

    // --- smoothing propagate: 10 layers, final straight to d_out ---
    {
        float* in = bufB; float* outp = bufA;
        for (int l = 0; l < 9; l++) {
            k_prop<<<gW, T>>>(in, outp, lastp, ALPHA_SMOOTH, 0.f, 1.f);
            float* t = in; in = outp; outp = t;
        }
        k_prop<<<gW, T>>>(in, out, lastp, ALPHA_SMOOTH, 0.f, 1.f);
    }
    (void)in_sizes; (void)n_in; (void)out_size;
}

// round 3
// speedup vs baseline: 1.0430x; 1.0430x over previous
#include <cuda_runtime.h>
#include <cuda_fp16.h>
#include <math.h>

#define Nn 100000
#define Ee 3200000
#define Cc 64
#define ALPHA_CORR 0.979f
#define ALPHA_SMOOTH 0.756f
#define SCAN_BLK 1024
#define SCAN_NBLK ((Nn + SCAN_BLK - 1) / SCAN_BLK)   // 98

// ---------------- static scratch (no dynamic allocation allowed) ----------------
__device__ float   g_bufA[Nn * Cc];        // fp32 correct-phase state
__device__ float   g_bufB[Nn * Cc];
__device__ float   g_last[Nn * Cc];        // fp32 last (correct phase)
__device__ __half2 g_hA[Nn * (Cc / 2)];    // fp16 smooth-phase state
__device__ __half2 g_hB[Nn * (Cc / 2)];
__device__ __half2 g_lasth[Nn * (Cc / 2)]; // fp16 last (smooth phase)
__device__ int     g_deg[Nn];
__device__ int     g_cnt[Nn];
__device__ int     g_rowptr[Nn + 1];
__device__ float   g_norm[Nn];
__device__ int     g_csr_src[Ee];
__device__ float   g_csr_w[Ee];
__device__ int     g_blocksums[128];
__device__ float   g_sumabs;
__device__ float   g_nummask;
__device__ int     g_mask_mode;   // 0=uint8, 1=int32, 2=float32

// ---------------- mask dtype detection ----------------
__global__ void k_detect(const void* __restrict__ mp) {
    if (threadIdx.x == 0 && blockIdx.x == 0) {
        const int*   ip = (const int*)mp;
        const float* fp = (const float*)mp;
        bool i_ok = true, f_ok = true;
        for (int i = 0; i < 1024; i++) {
            int v = ip[i];
            if (v != 0 && v != 1) i_ok = false;
            float f = fp[i];
            if (!(f == 0.0f || f == 1.0f)) f_ok = false;
        }
        g_mask_mode = i_ok ? 1 : (f_ok ? 2 : 0);
    }
}

__device__ __forceinline__ bool mask_at(const void* __restrict__ mp, int i) {
    int mode = g_mask_mode;
    if (mode == 1) return ((const int*)mp)[i] != 0;
    if (mode == 2) return ((const float*)mp)[i] != 0.0f;
    return ((const unsigned char*)mp)[i] != 0;
}

// ---------------- preprocessing ----------------
__global__ void k_init() {
    int i = blockIdx.x * blockDim.x + threadIdx.x;
    if (i < Nn) { g_deg[i] = 0; g_cnt[i] = 0; }
    if (i == 0) { g_sumabs = 0.f; g_nummask = 0.f; }
}

__global__ void k_hist(const int* __restrict__ dst) {
    int i = blockIdx.x * blockDim.x + threadIdx.x;
    if (i < Ee) atomicAdd(&g_deg[dst[i]], 1);
}

__global__ void k_scan_a() {
    __shared__ int sh[SCAN_BLK];
    int t = threadIdx.x;
    int i = blockIdx.x * SCAN_BLK + t;
    int v = (i < Nn) ? g_deg[i] : 0;
    sh[t] = v;
    __syncthreads();
    for (int off = 1; off < SCAN_BLK; off <<= 1) {
        int x = (t >= off) ? sh[t - off] : 0;
        __syncthreads();
        sh[t] += x;
        __syncthreads();
    }
    if (i < Nn) g_rowptr[i] = sh[t] - v;      // exclusive within block
    if (t == SCAN_BLK - 1) g_blocksums[blockIdx.x] = sh[t];
}

__global__ void k_scan_b() {
    int acc = 0;
    for (int b = 0; b < SCAN_NBLK; b++) {
        int s = g_blocksums[b];
        g_blocksums[b] = acc;
        acc += s;
    }
}

__global__ void k_scan_c() {
    int i = blockIdx.x * blockDim.x + threadIdx.x;
    if (i < Nn) g_rowptr[i] += g_blocksums[i / SCAN_BLK];
    if (i == 0) g_rowptr[Nn] = Ee;
}

__global__ void k_norm() {
    int i = blockIdx.x * blockDim.x + threadIdx.x;
    if (i < Nn) {
        float d = (float)g_deg[i];
        if (d < 1.f) d = 1.f;
        g_norm[i] = rsqrtf(d);
    }
}

__global__ void k_fill(const int* __restrict__ src, const int* __restrict__ dst) {
    int i = blockIdx.x * blockDim.x + threadIdx.x;
    if (i >= Ee) return;
    int d = dst[i];
    int s = src[i];
    int pos = g_rowptr[d] + atomicAdd(&g_cnt[d], 1);
    g_csr_src[pos] = s;
    g_csr_w[pos] = g_norm[s] * g_norm[d];
}

// ---------------- error + global reductions ----------------
__global__ void k_error(const float* __restrict__ ys, const float* __restrict__ yt,
                        const void* __restrict__ mask) {
    int idx = blockIdx.x * blockDim.x + threadIdx.x;
    float a = 0.f, cm = 0.f;
    if (idx < Nn * Cc) {
        int n = idx >> 6;
        float m = mask_at(mask, n) ? 1.f : 0.f;
        float e = m * (yt[idx] - ys[idx]);
        g_bufA[idx] = e;
        g_last[idx] = (1.f - ALPHA_CORR) * e;
        a = fabsf(e);
        if ((idx & (Cc - 1)) == 0) cm = m;
    }
    for (int o = 16; o; o >>= 1) {
        a  += __shfl_down_sync(0xffffffffu, a, o);
        cm += __shfl_down_sync(0xffffffffu, cm, o);
    }
    __shared__ float sa[8], sc[8];
    int warp = threadIdx.x >> 5, lane = threadIdx.x & 31;
    if (lane == 0) { sa[warp] = a; sc[warp] = cm; }
    __syncthreads();
    if (threadIdx.x == 0) {
        float ta = 0.f, tc = 0.f;
        int nw = blockDim.x >> 5;
        for (int w = 0; w < nw; w++) { ta += sa[w]; tc += sc[w]; }
        atomicAdd(&g_sumabs, ta);
        atomicAdd(&g_nummask, tc);
    }
}

// ---------------- combine (scale + blend); writes fp16 smooth-phase state ----------------
__global__ void k_combine(const float* __restrict__ ys, const float* __restrict__ yt,
                          const void* __restrict__ mask) {
    int w = (blockIdx.x * blockDim.x + threadIdx.x) >> 5;
    int lane = threadIdx.x & 31;
    if (w >= Nn) return;
    int base = w * Cc + 2 * lane;
    float2 sm = *(const float2*)(g_bufA + base);
    float part = fabsf(sm.x) + fabsf(sm.y);
    for (int o = 16; o; o >>= 1) part += __shfl_xor_sync(0xffffffffu, part, o);
    float sigma = g_sumabs / g_nummask;
    float scale = sigma / part;
    if (isinf(scale) || scale > 1000.f) scale = 1.f;
    float2 s = *(const float2*)(ys + base);
    float rx = s.x + scale * sm.x; if (isnan(rx)) rx = s.x;
    float ry = s.y + scale * sm.y; if (isnan(ry)) ry = s.y;
    if (mask_at(mask, w)) {
        float2 t = *(const float2*)(yt + base);
        rx = t.x; ry = t.y;
    }
    int hidx = w * (Cc / 2) + lane;
    g_hB[hidx]    = __float22half2_rn(make_float2(rx, ry));
    g_lasth[hidx] = __float22half2_rn(make_float2((1.f - ALPHA_SMOOTH) * rx,
                                                  (1.f - ALPHA_SMOOTH) * ry));
}

// ---------------- fp32 propagation layer (correct phase): warp per dst node ----------------
__global__ void k_prop(const float* __restrict__ yin, float* __restrict__ yout,
                       const float* __restrict__ last, float alpha, float lo, float hi) {
    int w = (blockIdx.x * blockDim.x + threadIdx.x) >> 5;
    int lane = threadIdx.x & 31;
    if (w >= Nn) return;
    int s0 = g_rowptr[w];
    int s1 = g_rowptr[w + 1];
    int nE = s1 - s0;
    float2 acc[4];
    acc[0] = make_float2(0.f, 0.f);
    acc[1] = make_float2(0.f, 0.f);
    acc[2] = make_float2(0.f, 0.f);
    acc[3] = make_float2(0.f, 0.f);

    for (int base = 0; base < nE; base += 32) {
        int e = s0 + base + lane;
        int sv = 0;
        float wv = 0.f;
        if (base + lane < nE) {
            sv = g_csr_src[e];
            wv = g_csr_w[e];
        }
        int cnt = nE - base;
        if (cnt > 32) cnt = 32;
        int cntr = (cnt + 3) & ~3;
        for (int j = 0; j < cntr; j += 4) {
#pragma unroll
            for (int u = 0; u < 4; u++) {
                int   ss = __shfl_sync(0xffffffffu, sv, j + u);
                float ww = __shfl_sync(0xffffffffu, wv, j + u);
                const float2 v = __ldg((const float2*)(yin + (size_t)ss * Cc) + lane);
                acc[u].x = fmaf(ww, v.x, acc[u].x);
                acc[u].y = fmaf(ww, v.y, acc[u].y);
            }
        }
    }
    float ax = (acc[0].x + acc[1].x) + (acc[2].x + acc[3].x);
    float ay = (acc[0].y + acc[1].y) + (acc[2].y + acc[3].y);

    const float2 l = __ldg((const float2*)(last + (size_t)w * Cc) + lane);
    float2 o;
    o.x = fminf(fmaxf(fmaf(alpha, ax, l.x), lo), hi);
    o.y = fminf(fmaxf(fmaf(alpha, ay, l.y), lo), hi);
    *((float2*)(yout + (size_t)w * Cc) + lane) = o;
}

// ---------------- fp16 propagation layer (smooth phase): warp per dst node ----------------
// Lane owns channels [2*lane, 2*lane+1] as one __half2 (row = 128B, fully coalesced).
// Accumulation fp32. If out_f != nullptr this is the final layer: write fp32 to d_out.
__global__ void k_prop_h(const __half2* __restrict__ yin, __half2* __restrict__ yout,
                         float* __restrict__ out_f,
                         const __half2* __restrict__ last, float alpha, float lo, float hi) {
    int w = (blockIdx.x * blockDim.x + threadIdx.x) >> 5;
    int lane = threadIdx.x & 31;
    if (w >= Nn) return;
    int s0 = g_rowptr[w];
    int s1 = g_rowptr[w + 1];
    int nE = s1 - s0;
    float2 acc[4];
    acc[0] = make_float2(0.f, 0.f);
    acc[1] = make_float2(0.f, 0.f);
    acc[2] = make_float2(0.f, 0.f);
    acc[3] = make_float2(0.f, 0.f);

    for (int base = 0; base < nE; base += 32) {
        int e = s0 + base + lane;
        int sv = 0;
        float wv = 0.f;
        if (base + lane < nE) {
            sv = g_csr_src[e];
            wv = g_csr_w[e];
        }
        int cnt = nE - base;
        if (cnt > 32) cnt = 32;
        int cntr = (cnt + 3) & ~3;
        for (int j = 0; j < cntr; j += 4) {
#pragma unroll
            for (int u = 0; u < 4; u++) {
                int   ss = __shfl_sync(0xffffffffu, sv, j + u);
                float ww = __shfl_sync(0xffffffffu, wv, j + u);
                const __half2 h = __ldg(yin + (size_t)ss * (Cc / 2) + lane);
                float2 v = __half22float2(h);
                acc[u].x = fmaf(ww, v.x, acc[u].x);
                acc[u].y = fmaf(ww, v.y, acc[u].y);
            }
        }
    }
    float ax = (acc[0].x + acc[1].x) + (acc[2].x + acc[3].x);
    float ay = (acc[0].y + acc[1].y) + (acc[2].y + acc[3].y);

    float2 l = __half22float2(__ldg(last + (size_t)w * (Cc / 2) + lane));
    float ox = fminf(fmaxf(fmaf(alpha, ax, l.x), lo), hi);
    float oy = fminf(fmaxf(fmaf(alpha, ay, l.y), lo), hi);
    if (out_f) {
        *((float2*)(out_f + (size_t)w * Cc) + lane) = make_float2(ox, oy);
    } else {
        yout[(size_t)w * (Cc / 2) + lane] = __float22half2_rn(make_float2(ox, oy));
    }
}

// ---------------- launch ----------------
extern "C" void kernel_launch(void* const* d_in, const int* in_sizes, int n_in,
                              void* d_out, int out_size) {
    const float* y_soft = (const float*)d_in[0];
    const float* y_true = (const float*)d_in[1];
    const int*   src    = (const int*)d_in[2];
    const int*   dst    = (const int*)d_in[3];
    const void*  mask   = (const void*)d_in[4];
    float* out = (float*)d_out;

    const int T = 256;
    const int gN  = (Nn + T - 1) / T;
    const int gE  = (Ee + T - 1) / T;
    const int gNC = (Nn * Cc + T - 1) / T;
    const int gW  = (Nn * 32 + T - 1) / T;   // warp-per-node grids

    float* bufA; float* bufB; float* lastp;
    __half2* hA; __half2* hB; __half2* lasth;
    cudaGetSymbolAddress((void**)&bufA, g_bufA);
    cudaGetSymbolAddress((void**)&bufB, g_bufB);
    cudaGetSymbolAddress((void**)&lastp, g_last);
    cudaGetSymbolAddress((void**)&hA, g_hA);
    cudaGetSymbolAddress((void**)&hB, g_hB);
    cudaGetSymbolAddress((void**)&lasth, g_lasth);

    // --- mask dtype detection ---
    k_detect<<<1, 32>>>(mask);

    // --- preprocessing: degrees, CSR, norms ---
    k_init<<<gN, T>>>();
    k_hist<<<gE, T>>>(dst);
    k_scan_a<<<SCAN_NBLK, SCAN_BLK>>>();
    k_scan_b<<<1, 1>>>();
    k_scan_c<<<gN, T>>>();
    k_norm<<<gN, T>>>();
    k_fill<<<gE, T>>>(src, dst);

    // --- error + sums ---
    k_error<<<gNC, T>>>(y_soft, y_true, mask);

    // --- correction propagate (fp32): 10 layers, result ends in bufA ---
    {
        float* in = bufA; float* outp = bufB;
        for (int l = 0; l < 10; l++) {
            k_prop<<<gW, T>>>(in, outp, lastp, ALPHA_CORR, -1.f, 1.f);
            float* t = in; in = outp; outp = t;
        }
    }

    // --- combine: reads bufA (smoothed error), writes hB (fp16 y) + lasth ---
    k_combine<<<gW, T>>>(y_soft, y_true, mask);

    // --- smoothing propagate (fp16): 10 layers, final writes fp32 to d_out ---
    {
        __half2* in = hB; __half2* outp = hA;
        for (int l = 0; l < 9; l++) {
            k_prop_h<<<gW, T>>>(in, outp, (float*)0, lasth, ALPHA_SMOOTH, 0.f, 1.f);
            __half2* t = in; in = outp; outp = t;
        }
        k_prop_h<<<gW, T>>>(in, (__half2*)0, out, lasth, ALPHA_SMOOTH, 0.f, 1.f);
    }
    (void)in_sizes; (void)n_in; (void)out_size;
}

// round 4
// speedup vs baseline: 1.6932x; 1.6234x over previous
#include <cuda_runtime.h>
#include <cuda_fp16.h>
#include <math.h>

#define Nn 100000
#define Ee 3200000
#define Cc 64
#define ALPHA_CORR 0.979f
#define ALPHA_SMOOTH 0.756f
#define SCAN_BLK 1024
#define SCAN_NBLK ((Nn + SCAN_BLK - 1) / SCAN_BLK)   // 98

// ---------------- static scratch ----------------
// fp16 state rows: 64 halfs = 128B = 8 uint4 per node
__device__ uint4  g_hA[Nn * 8];
__device__ uint4  g_hB[Nn * 8];
__device__ uint4  g_lasth[Nn * 8];
__device__ int    g_deg[Nn];
__device__ int    g_cnt[Nn];
__device__ int    g_rowptr[Nn + 1];
__device__ float  g_norm[Nn];
__device__ int2   g_csr[Ee];          // (src, __float_as_int(w)) interleaved
__device__ int    g_blocksums[128];
__device__ float  g_sumabs;
__device__ float  g_nummask;
__device__ int    g_mask_mode;        // 0=uint8, 1=int32, 2=float32

// ---------------- mask dtype detection ----------------
__global__ void k_detect(const void* __restrict__ mp) {
    if (threadIdx.x == 0 && blockIdx.x == 0) {
        const int*   ip = (const int*)mp;
        const float* fp = (const float*)mp;
        bool i_ok = true, f_ok = true;
        for (int i = 0; i < 1024; i++) {
            int v = ip[i];
            if (v != 0 && v != 1) i_ok = false;
            float f = fp[i];
            if (!(f == 0.0f || f == 1.0f)) f_ok = false;
        }
        g_mask_mode = i_ok ? 1 : (f_ok ? 2 : 0);
    }
}

__device__ __forceinline__ bool mask_at(const void* __restrict__ mp, int i) {
    int mode = g_mask_mode;
    if (mode == 1) return ((const int*)mp)[i] != 0;
    if (mode == 2) return ((const float*)mp)[i] != 0.0f;
    return ((const unsigned char*)mp)[i] != 0;
}

// ---------------- preprocessing ----------------
__global__ void k_init() {
    int i = blockIdx.x * blockDim.x + threadIdx.x;
    if (i < Nn) { g_deg[i] = 0; g_cnt[i] = 0; }
    if (i == 0) { g_sumabs = 0.f; g_nummask = 0.f; }
}

__global__ void k_hist(const int* __restrict__ dst) {
    int i = blockIdx.x * blockDim.x + threadIdx.x;
    if (i < Ee) atomicAdd(&g_deg[dst[i]], 1);
}

__global__ void k_scan_a() {
    __shared__ int sh[SCAN_BLK];
    int t = threadIdx.x;
    int i = blockIdx.x * SCAN_BLK + t;
    int v = (i < Nn) ? g_deg[i] : 0;
    sh[t] = v;
    __syncthreads();
    for (int off = 1; off < SCAN_BLK; off <<= 1) {
        int x = (t >= off) ? sh[t - off] : 0;
        __syncthreads();
        sh[t] += x;
        __syncthreads();
    }
    if (i < Nn) g_rowptr[i] = sh[t] - v;
    if (t == SCAN_BLK - 1) g_blocksums[blockIdx.x] = sh[t];
}

__global__ void k_scan_b() {
    int acc = 0;
    for (int b = 0; b < SCAN_NBLK; b++) {
        int s = g_blocksums[b];
        g_blocksums[b] = acc;
        acc += s;
    }
}

// scan_c + norm fused
__global__ void k_scan_c() {
    int i = blockIdx.x * blockDim.x + threadIdx.x;
    if (i < Nn) {
        g_rowptr[i] += g_blocksums[i / SCAN_BLK];
        float d = (float)g_deg[i];
        if (d < 1.f) d = 1.f;
        g_norm[i] = rsqrtf(d);
    }
    if (i == 0) g_rowptr[Nn] = Ee;
}

__global__ void k_fill(const int* __restrict__ src, const int* __restrict__ dst) {
    int i = blockIdx.x * blockDim.x + threadIdx.x;
    if (i >= Ee) return;
    int d = dst[i];
    int s = src[i];
    int pos = g_rowptr[d] + atomicAdd(&g_cnt[d], 1);
    g_csr[pos] = make_int2(s, __float_as_int(g_norm[s] * g_norm[d]));
}

// ---------------- error (fp16 out) + global reductions ----------------
// one thread per half2 pair (Nn*32 threads)
__global__ void k_error(const float* __restrict__ ys, const float* __restrict__ yt,
                        const void* __restrict__ mask) {
    int idx = blockIdx.x * blockDim.x + threadIdx.x;
    float a = 0.f, cm = 0.f;
    if (idx < Nn * 32) {
        int n = idx >> 5;
        float m = mask_at(mask, n) ? 1.f : 0.f;
        float2 s = *(const float2*)(ys + 2 * idx);
        float2 t = *(const float2*)(yt + 2 * idx);
        float e0 = m * (t.x - s.x);
        float e1 = m * (t.y - s.y);
        ((__half2*)g_hA)[idx]    = __floats2half2_rn(e0, e1);
        ((__half2*)g_lasth)[idx] = __floats2half2_rn((1.f - ALPHA_CORR) * e0,
                                                     (1.f - ALPHA_CORR) * e1);
        a = fabsf(e0) + fabsf(e1);
        if ((idx & 31) == 0) cm = m;
    }
    for (int o = 16; o; o >>= 1) {
        a  += __shfl_down_sync(0xffffffffu, a, o);
        cm += __shfl_down_sync(0xffffffffu, cm, o);
    }
    __shared__ float sa[8], sc[8];
    int warp = threadIdx.x >> 5, lane = threadIdx.x & 31;
    if (lane == 0) { sa[warp] = a; sc[warp] = cm; }
    __syncthreads();
    if (threadIdx.x == 0) {
        float ta = 0.f, tc = 0.f;
        int nw = blockDim.x >> 5;
        for (int w = 0; w < nw; w++) { ta += sa[w]; tc += sc[w]; }
        atomicAdd(&g_sumabs, ta);
        atomicAdd(&g_nummask, tc);
    }
}

// ---------------- combine (scale + blend); hA(smoothed err) -> hB(y), lasth ----------------
__global__ void k_combine(const float* __restrict__ ys, const float* __restrict__ yt,
                          const void* __restrict__ mask) {
    int w = (blockIdx.x * blockDim.x + threadIdx.x) >> 5;
    int lane = threadIdx.x & 31;
    if (w >= Nn) return;
    int idx = w * 32 + lane;
    float2 sm = __half22float2(((const __half2*)g_hA)[idx]);
    float part = fabsf(sm.x) + fabsf(sm.y);
    for (int o = 16; o; o >>= 1) part += __shfl_xor_sync(0xffffffffu, part, o);
    float sigma = g_sumabs / g_nummask;
    float scale = sigma / part;
    if (isinf(scale) || scale > 1000.f) scale = 1.f;
    int base = w * Cc + 2 * lane;
    float2 s = *(const float2*)(ys + base);
    float rx = s.x + scale * sm.x; if (isnan(rx)) rx = s.x;
    float ry = s.y + scale * sm.y; if (isnan(ry)) ry = s.y;
    if (mask_at(mask, w)) {
        float2 t = *(const float2*)(yt + base);
        rx = t.x; ry = t.y;
    }
    ((__half2*)g_hB)[idx]    = __floats2half2_rn(rx, ry);
    ((__half2*)g_lasth)[idx] = __floats2half2_rn((1.f - ALPHA_SMOOTH) * rx,
                                                 (1.f - ALPHA_SMOOTH) * ry);
}

// ---------------- fp16 propagation layer: warp per node, 8 lanes per edge-row ----------------
// group = lane>>3 (4 groups), k = lane&7. Each LDG.128 covers 4 edges' rows.
// Accumulate fp32 (8 channels per lane), cross-group reduce at end.
// If out_f != nullptr: final layer, write fp32 to out_f.
__global__ void k_prop16(const uint4* __restrict__ yin, uint4* __restrict__ yout,
                         float* __restrict__ out_f,
                         const uint4* __restrict__ last, float alpha, float lo, float hi) {
    int w = (blockIdx.x * blockDim.x + threadIdx.x) >> 5;
    int lane = threadIdx.x & 31;
    if (w >= Nn) return;
    int grp = lane >> 3;      // 0..3
    int k   = lane & 7;       // 0..7

    int s0 = g_rowptr[w];
    int nE = g_rowptr[w + 1] - s0;

    float acc0 = 0.f, acc1 = 0.f, acc2 = 0.f, acc3 = 0.f;
    float acc4 = 0.f, acc5 = 0.f, acc6 = 0.f, acc7 = 0.f;

    for (int base = 0; base < nE; base += 32) {
        int sv = 0;
        float wv = 0.f;
        if (base + lane < nE) {
            int2 ev = __ldg(&g_csr[s0 + base + lane]);
            sv = ev.x;
            wv = __int_as_float(ev.y);
        }
        int cnt = nE - base;
        if (cnt > 32) cnt = 32;
        for (int j = 0; j < cnt; j += 4) {
            int sel = j + grp;                       // <= 31 always
            int   ss = __shfl_sync(0xffffffffu, sv, sel);
            float ww = __shfl_sync(0xffffffffu, wv, sel);   // 0 for padded lanes
            uint4 h = __ldg(yin + (size_t)ss * 8 + k);
            float2 v0 = __half22float2(*(const __half2*)&h.x);
            float2 v1 = __half22float2(*(const __half2*)&h.y);
            float2 v2 = __half22float2(*(const __half2*)&h.z);
            float2 v3 = __half22float2(*(const __half2*)&h.w);
            acc0 = fmaf(ww, v0.x, acc0);
            acc1 = fmaf(ww, v0.y, acc1);
            acc2 = fmaf(ww, v1.x, acc2);
            acc3 = fmaf(ww, v1.y, acc3);
            acc4 = fmaf(ww, v2.x, acc4);
            acc5 = fmaf(ww, v2.y, acc5);
            acc6 = fmaf(ww, v3.x, acc6);
            acc7 = fmaf(ww, v3.y, acc7);
        }
    }

    // cross-group reduction: lanes {k, k+8, k+16, k+24} hold partials of same channels
#pragma unroll
    for (int o = 8; o <= 16; o <<= 1) {
        acc0 += __shfl_xor_sync(0xffffffffu, acc0, o);
        acc1 += __shfl_xor_sync(0xffffffffu, acc1, o);
        acc2 += __shfl_xor_sync(0xffffffffu, acc2, o);
        acc3 += __shfl_xor_sync(0xffffffffu, acc3, o);
        acc4 += __shfl_xor_sync(0xffffffffu, acc4, o);
        acc5 += __shfl_xor_sync(0xffffffffu, acc5, o);
        acc6 += __shfl_xor_sync(0xffffffffu, acc6, o);
        acc7 += __shfl_xor_sync(0xffffffffu, acc7, o);
    }

    if (grp == 0) {   // lanes 0..7 hold full sums for channels [8k, 8k+8)
        uint4 lh = __ldg(last + (size_t)w * 8 + k);
        float2 l0 = __half22float2(*(const __half2*)&lh.x);
        float2 l1 = __half22float2(*(const __half2*)&lh.y);
        float2 l2 = __half22float2(*(const __half2*)&lh.z);
        float2 l3 = __half22float2(*(const __half2*)&lh.w);
        float o0 = fminf(fmaxf(fmaf(alpha, acc0, l0.x), lo), hi);
        float o1 = fminf(fmaxf(fmaf(alpha, acc1, l0.y), lo), hi);
        float o2 = fminf(fmaxf(fmaf(alpha, acc2, l1.x), lo), hi);
        float o3 = fminf(fmaxf(fmaf(alpha, acc3, l1.y), lo), hi);
        float o4 = fminf(fmaxf(fmaf(alpha, acc4, l2.x), lo), hi);
        float o5 = fminf(fmaxf(fmaf(alpha, acc5, l2.y), lo), hi);
        float o6 = fminf(fmaxf(fmaf(alpha, acc6, l3.x), lo), hi);
        float o7 = fminf(fmaxf(fmaf(alpha, acc7, l3.y), lo), hi);
        if (out_f) {
            float* op = out_f + (size_t)w * Cc + 8 * k;
            *(float4*)(op)     = make_float4(o0, o1, o2, o3);
            *(float4*)(op + 4) = make_float4(o4, o5, o6, o7);
        } else {
            uint4 hout;
            *(__half2*)&hout.x = __floats2half2_rn(o0, o1);
            *(__half2*)&hout.y = __floats2half2_rn(o2, o3);
            *(__half2*)&hout.z = __floats2half2_rn(o4, o5);
            *(__half2*)&hout.w = __floats2half2_rn(o6, o7);
            yout[(size_t)w * 8 + k] = hout;
        }
    }
}

// ---------------- launch ----------------
extern "C" void kernel_launch(void* const* d_in, const int* in_sizes, int n_in,
                              void* d_out, int out_size) {
    const float* y_soft = (const float*)d_in[0];
    const float* y_true = (const float*)d_in[1];
    const int*   src    = (const int*)d_in[2];
    const int*   dst    = (const int*)d_in[3];
    const void*  mask   = (const void*)d_in[4];
    float* out = (float*)d_out;

    const int T = 256;
    const int gN  = (Nn + T - 1) / T;
    const int gE  = (Ee + T - 1) / T;
    const int gH  = (Nn * 32 + T - 1) / T;   // one thread per half2
    const int gW  = (Nn * 32 + T - 1) / T;   // warp per node

    uint4 *hA, *hB, *lasth;
    cudaGetSymbolAddress((void**)&hA, g_hA);
    cudaGetSymbolAddress((void**)&hB, g_hB);
    cudaGetSymbolAddress((void**)&lasth, g_lasth);

    k_detect<<<1, 32>>>(mask);

    // preprocessing
    k_init<<<gN, T>>>();
    k_hist<<<gE, T>>>(dst);
    k_scan_a<<<SCAN_NBLK, SCAN_BLK>>>();
    k_scan_b<<<1, 1>>>();
    k_scan_c<<<gN, T>>>();
    k_fill<<<gE, T>>>(src, dst);

    // error (fp16) + sums
    k_error<<<gH, T>>>(y_soft, y_true, mask);

    // correct phase: 10 layers, hA -> ... -> hA
    {
        uint4* in = hA; uint4* outp = hB;
        for (int l = 0; l < 10; l++) {
            k_prop16<<<gW, T>>>(in, outp, (float*)0, lasth, ALPHA_CORR, -1.f, 1.f);
            uint4* t = in; in = outp; outp = t;
        }
    }

    // combine: hA -> hB (y), lasth overwritten for smooth phase
    k_combine<<<gW, T>>>(y_soft, y_true, mask);

    // smooth phase: 10 layers, final writes fp32 to d_out
    {
        uint4* in = hB; uint4* outp = hA;
        for (int l = 0; l < 9; l++) {
            k_prop16<<<gW, T>>>(in, outp, (float*)0, lasth, ALPHA_SMOOTH, 0.f, 1.f);
            uint4* t = in; in = outp; outp = t;
        }
        k_prop16<<<gW, T>>>(in, (uint4*)0, out, lasth, ALPHA_SMOOTH, 0.f, 1.f);
    }
    (void)in_sizes; (void)n_in; (void)out_size;
}

// round 5
// speedup vs baseline: 1.7223x; 1.0172x over previous
#include <cuda_runtime.h>
#include <cuda_fp16.h>
#include <math.h>

#define Nn 100000
#define Ee 3200000
#define Cc 64
#define ALPHA_CORR 0.979f
#define ALPHA_SMOOTH 0.756f
#define SCAN_BLK 1024
#define SCAN_NBLK ((Nn + SCAN_BLK - 1) / SCAN_BLK)   // 98
#define GN ((Nn + 255) / 256)                        // 391

// ---------------- static scratch ----------------
__device__ uint4    g_hA[Nn * 8];      // fp16 state rows: 64 halfs = 128B = 8 uint4
__device__ uint4    g_hB[Nn * 8];
__device__ uint4    g_lasth[Nn * 8];
__device__ int      g_deg[Nn];
__device__ int      g_cnt[Nn];
__device__ int      g_rowptr[Nn + 1];
__device__ int      g_wq[Nn];          // 15-bit quantized norm per node
__device__ unsigned g_csr[Ee];         // (wq<<17) | src  — 4B per edge
__device__ int      g_blocksums[128];
__device__ float    g_sumabs;
__device__ float    g_nummask;
__device__ int      g_mask_mode;       // 0=uint8, 1=int32, 2=float32

__device__ __forceinline__ bool mask_at(const void* __restrict__ mp, int i) {
    int mode = g_mask_mode;
    if (mode == 1) return ((const int*)mp)[i] != 0;
    if (mode == 2) return ((const float*)mp)[i] != 0.0f;
    return ((const unsigned char*)mp)[i] != 0;
}

// ---------------- init + mask dtype detection (block 0) ----------------
__global__ void k_init(const void* __restrict__ mp) {
    int i = blockIdx.x * blockDim.x + threadIdx.x;
    if (i < Nn) { g_deg[i] = 0; g_cnt[i] = 0; }
    if (i == 0) { g_sumabs = 0.f; g_nummask = 0.f; }
    if (blockIdx.x == 0) {
        __shared__ int s_iok, s_fok;
        if (threadIdx.x == 0) { s_iok = 1; s_fok = 1; }
        __syncthreads();
        const int*   ip = (const int*)mp;
        const float* fp = (const float*)mp;
        bool iok = true, fok = true;
        for (int j = threadIdx.x; j < 1024; j += 256) {
            int v = ip[j];
            if (v != 0 && v != 1) iok = false;
            float f = fp[j];
            if (!(f == 0.0f || f == 1.0f)) fok = false;
        }
        if (!iok) s_iok = 0;
        if (!fok) s_fok = 0;
        __syncthreads();
        if (threadIdx.x == 0) g_mask_mode = s_iok ? 1 : (s_fok ? 2 : 0);
    }
}

// ---------------- degree histogram (4 edges / thread) ----------------
__global__ void k_hist(const int4* __restrict__ dst4) {
    int i = blockIdx.x * blockDim.x + threadIdx.x;
    if (i < Ee / 4) {
        int4 d = __ldg(&dst4[i]);
        atomicAdd(&g_deg[d.x], 1);
        atomicAdd(&g_deg[d.y], 1);
        atomicAdd(&g_deg[d.z], 1);
        atomicAdd(&g_deg[d.w], 1);
    }
}

// ---------------- block-local scan ----------------
__global__ void k_scan_a() {
    __shared__ int sh[SCAN_BLK];
    int t = threadIdx.x;
    int i = blockIdx.x * SCAN_BLK + t;
    int v = (i < Nn) ? g_deg[i] : 0;
    sh[t] = v;
    __syncthreads();
    for (int off = 1; off < SCAN_BLK; off <<= 1) {
        int x = (t >= off) ? sh[t - off] : 0;
        __syncthreads();
        sh[t] += x;
        __syncthreads();
    }
    if (i < Nn) g_rowptr[i] = sh[t] - v;      // exclusive within block
    if (t == SCAN_BLK - 1) g_blocksums[blockIdx.x] = sh[t];
}

// ---------------- fused: scan finalize + norm quant + error + reductions ----------------
// grid = Nn*32/256 blocks. Blocks < GN also finalize rowptr/wq for 256 nodes each.
__global__ void k_scanbc_error(const float* __restrict__ ys, const float* __restrict__ yt,
                               const void* __restrict__ mask) {
    int t = threadIdx.x;
    int b = blockIdx.x;

    if (b < GN) {
        __shared__ int sh[128];
        if (t < 128) sh[t] = (t < SCAN_NBLK) ? g_blocksums[t] : 0;
        __syncthreads();
        for (int off = 1; off < 128; off <<= 1) {
            int x = (t >= off && t < 128) ? sh[t - off] : 0;
            __syncthreads();
            if (t < 128) sh[t] += x;
            __syncthreads();
        }
        int i = b * 256 + t;
        if (i < Nn) {
            int blk = i >> 10;
            int add = blk ? sh[blk - 1] : 0;
            g_rowptr[i] += add;
            int d = g_deg[i]; if (d < 1) d = 1;
            g_wq[i] = (int)(rsqrtf((float)d) * 32767.f + 0.5f);
        }
        if (i == 0) g_rowptr[Nn] = Ee;
        __syncthreads();
    }

    // error part: one thread per half2 pair
    int idx = b * 256 + t;
    float a = 0.f, cm = 0.f;
    if (idx < Nn * 32) {
        int n = idx >> 5;
        float m = mask_at(mask, n) ? 1.f : 0.f;
        float2 s = *(const float2*)(ys + 2 * idx);
        float2 tt = *(const float2*)(yt + 2 * idx);
        float e0 = m * (tt.x - s.x);
        float e1 = m * (tt.y - s.y);
        ((__half2*)g_hA)[idx]    = __floats2half2_rn(e0, e1);
        ((__half2*)g_lasth)[idx] = __floats2half2_rn((1.f - ALPHA_CORR) * e0,
                                                     (1.f - ALPHA_CORR) * e1);
        a = fabsf(e0) + fabsf(e1);
        if ((idx & 31) == 0) cm = m;
    }
    for (int o = 16; o; o >>= 1) {
        a  += __shfl_down_sync(0xffffffffu, a, o);
        cm += __shfl_down_sync(0xffffffffu, cm, o);
    }
    __shared__ float sa[8], sc[8];
    int warp = t >> 5, lane = t & 31;
    if (lane == 0) { sa[warp] = a; sc[warp] = cm; }
    __syncthreads();
    if (t == 0) {
        float ta = 0.f, tc = 0.f;
        for (int w = 0; w < 8; w++) { ta += sa[w]; tc += sc[w]; }
        atomicAdd(&g_sumabs, ta);
        atomicAdd(&g_nummask, tc);
    }
}

// ---------------- CSR fill (packed 4B) ----------------
__global__ void k_fill(const int* __restrict__ src, const int* __restrict__ dst) {
    int i = blockIdx.x * blockDim.x + threadIdx.x;
    if (i >= Ee) return;
    int d = dst[i];
    int s = src[i];
    int pos = g_rowptr[d] + atomicAdd(&g_cnt[d], 1);
    g_csr[pos] = ((unsigned)g_wq[s] << 17) | (unsigned)s;
}

// ---------------- combine (scale + blend) ----------------
__global__ void k_combine(const float* __restrict__ ys, const float* __restrict__ yt,
                          const void* __restrict__ mask) {
    int w = (blockIdx.x * blockDim.x + threadIdx.x) >> 5;
    int lane = threadIdx.x & 31;
    if (w >= Nn) return;
    int idx = w * 32 + lane;
    float2 sm = __half22float2(((const __half2*)g_hA)[idx]);
    float part = fabsf(sm.x) + fabsf(sm.y);
    for (int o = 16; o; o >>= 1) part += __shfl_xor_sync(0xffffffffu, part, o);
    float sigma = g_sumabs / g_nummask;
    float scale = sigma / part;
    if (isinf(scale) || scale > 1000.f) scale = 1.f;
    int base = w * Cc + 2 * lane;
    float2 s = *(const float2*)(ys + base);
    float rx = s.x + scale * sm.x; if (isnan(rx)) rx = s.x;
    float ry = s.y + scale * sm.y; if (isnan(ry)) ry = s.y;
    if (mask_at(mask, w)) {
        float2 t = *(const float2*)(yt + base);
        rx = t.x; ry = t.y;
    }
    ((__half2*)g_hB)[idx]    = __floats2half2_rn(rx, ry);
    ((__half2*)g_lasth)[idx] = __floats2half2_rn((1.f - ALPHA_SMOOTH) * rx,
                                                 (1.f - ALPHA_SMOOTH) * ry);
}

// ---------------- fp16 propagation layer: warp per node, 8 lanes per edge-row ----------------
__global__ void k_prop16(const uint4* __restrict__ yin, uint4* __restrict__ yout,
                         float* __restrict__ out_f,
                         const uint4* __restrict__ last, float alpha, float lo, float hi) {
    int w = (blockIdx.x * blockDim.x + threadIdx.x) >> 5;
    int lane = threadIdx.x & 31;
    if (w >= Nn) return;
    int grp = lane >> 3;      // 0..3
    int k   = lane & 7;       // 0..7

    int s0 = g_rowptr[w];
    int nE = g_rowptr[w + 1] - s0;

    float acc0 = 0.f, acc1 = 0.f, acc2 = 0.f, acc3 = 0.f;
    float acc4 = 0.f, acc5 = 0.f, acc6 = 0.f, acc7 = 0.f;

    for (int base = 0; base < nE; base += 32) {
        unsigned packed = 0;   // src=0, w=0: harmless
        if (base + lane < nE) packed = __ldg(&g_csr[s0 + base + lane]);
        int cnt = nE - base;
        if (cnt > 32) cnt = 32;
        for (int j = 0; j < cnt; j += 4) {
            unsigned p = __shfl_sync(0xffffffffu, packed, j + grp);
            int   ss = (int)(p & 0x1FFFFu);
            float ww = (float)(p >> 17);           // 1/32767 folded into final scale
            uint4 h = __ldg(yin + (size_t)ss * 8 + k);
            float2 v0 = __half22float2(*(const __half2*)&h.x);
            float2 v1 = __half22float2(*(const __half2*)&h.y);
            float2 v2 = __half22float2(*(const __half2*)&h.z);
            float2 v3 = __half22float2(*(const __half2*)&h.w);
            acc0 = fmaf(ww, v0.x, acc0);
            acc1 = fmaf(ww, v0.y, acc1);
            acc2 = fmaf(ww, v1.x, acc2);
            acc3 = fmaf(ww, v1.y, acc3);
            acc4 = fmaf(ww, v2.x, acc4);
            acc5 = fmaf(ww, v2.y, acc5);
            acc6 = fmaf(ww, v3.x, acc6);
            acc7 = fmaf(ww, v3.y, acc7);
        }
    }

#pragma unroll
    for (int o = 8; o <= 16; o <<= 1) {
        acc0 += __shfl_xor_sync(0xffffffffu, acc0, o);
        acc1 += __shfl_xor_sync(0xffffffffu, acc1, o);
        acc2 += __shfl_xor_sync(0xffffffffu, acc2, o);
        acc3 += __shfl_xor_sync(0xffffffffu, acc3, o);
        acc4 += __shfl_xor_sync(0xffffffffu, acc4, o);
        acc5 += __shfl_xor_sync(0xffffffffu, acc5, o);
        acc6 += __shfl_xor_sync(0xffffffffu, acc6, o);
        acc7 += __shfl_xor_sync(0xffffffffu, acc7, o);
    }

    if (grp == 0) {
        // alpha * norm[dst] * (1/32767), norm[dst] = rsqrt(max(deg,1)), deg = nE
        float nd = rsqrtf((float)(nE < 1 ? 1 : nE));
        float sc = alpha * nd * (1.0f / 32767.0f);
        uint4 lh = __ldg(last + (size_t)w * 8 + k);
        float2 l0 = __half22float2(*(const __half2*)&lh.x);
        float2 l1 = __half22float2(*(const __half2*)&lh.y);
        float2 l2 = __half22float2(*(const __half2*)&lh.z);
        float2 l3 = __half22float2(*(const __half2*)&lh.w);
        float o0 = fminf(fmaxf(fmaf(sc, acc0, l0.x), lo), hi);
        float o1 = fminf(fmaxf(fmaf(sc, acc1, l0.y), lo), hi);
        float o2 = fminf(fmaxf(fmaf(sc, acc2, l1.x), lo), hi);
        float o3 = fminf(fmaxf(fmaf(sc, acc3, l1.y), lo), hi);
        float o4 = fminf(fmaxf(fmaf(sc, acc4, l2.x), lo), hi);
        float o5 = fminf(fmaxf(fmaf(sc, acc5, l2.y), lo), hi);
        float o6 = fminf(fmaxf(fmaf(sc, acc6, l3.x), lo), hi);
        float o7 = fminf(fmaxf(fmaf(sc, acc7, l3.y), lo), hi);
        if (out_f) {
            float* op = out_f + (size_t)w * Cc + 8 * k;
            *(float4*)(op)     = make_float4(o0, o1, o2, o3);
            *(float4*)(op + 4) = make_float4(o4, o5, o6, o7);
        } else {
            uint4 hout;
            *(__half2*)&hout.x = __floats2half2_rn(o0, o1);
            *(__half2*)&hout.y = __floats2half2_rn(o2, o3);
            *(__half2*)&hout.z = __floats2half2_rn(o4, o5);
            *(__half2*)&hout.w = __floats2half2_rn(o6, o7);
            yout[(size_t)w * 8 + k] = hout;
        }
    }
}

// ---------------- launch ----------------
extern "C" void kernel_launch(void* const* d_in, const int* in_sizes, int n_in,
                              void* d_out, int out_size) {
    const float* y_soft = (const float*)d_in[0];
    const float* y_true = (const float*)d_in[1];
    const int*   src    = (const int*)d_in[2];
    const int*   dst    = (const int*)d_in[3];
    const void*  mask   = (const void*)d_in[4];
    float* out = (float*)d_out;

    const int T = 256;
    const int gN  = GN;
    const int gE  = (Ee + T - 1) / T;
    const int gE4 = (Ee / 4 + T - 1) / T;
    const int gW  = (Nn * 32 + T - 1) / T;   // warp per node / thread per half2

    uint4 *hA, *hB, *lasth;
    cudaGetSymbolAddress((void**)&hA, g_hA);
    cudaGetSymbolAddress((void**)&hB, g_hB);
    cudaGetSymbolAddress((void**)&lasth, g_lasth);

    // preprocessing (5 launches before first prop)
    k_init<<<gN, T>>>(mask);                          // 0: init + mask detect
    k_hist<<<gE4, T>>>((const int4*)dst);             // 1
    k_scan_a<<<SCAN_NBLK, SCAN_BLK>>>();              // 2
    k_scanbc_error<<<gW, T>>>(y_soft, y_true, mask);  // 3: scan finalize + wq + error
    k_fill<<<gE, T>>>(src, dst);                      // 4

    // correct phase: 10 layers, hA -> ... -> hA      // 5..14
    {
        uint4* in = hA; uint4* outp = hB;
        for (int l = 0; l < 10; l++) {
            k_prop16<<<gW, T>>>(in, outp, (float*)0, lasth, ALPHA_CORR, -1.f, 1.f);
            uint4* t = in; in = outp; outp = t;
        }
    }

    // combine: hA -> hB (y), lasth for smooth phase  // 15
    k_combine<<<gW, T>>>(y_soft, y_true, mask);

    // smooth phase: 10 layers, final writes fp32     // 16..25
    {
        uint4* in = hB; uint4* outp = hA;
        for (int l = 0; l < 9; l++) {
            k_prop16<<<gW, T>>>(in, outp, (float*)0, lasth, ALPHA_SMOOTH, 0.f, 1.f);
            uint4* t = in; in = outp; outp = t;
        }
        k_prop16<<<gW, T>>>(in, (uint4*)0, out, lasth, ALPHA_SMOOTH, 0.f, 1.f);
    }
    (void)in_sizes; (void)n_in; (void)out_size;
}